// round 10
// baseline (speedup 1.0000x reference)
#include <cuda_runtime.h>
#include <cuda_fp16.h>
#include <cstdint>

// ============================================================================
// PointPairwiseRelation3 — fp16 mma.sync m16n8k16
//   A-gen via HADD2+HMAX2, mean-half via f16-out MMA + staged f16 accum
//   flushed to f32 every 8 tiles.
//
//   pre[b,n,j,k,o] = base[b,n,o] + U1[b,j,o] + U2[b,k,o]
//   h = relu(pre);  u = relu(h @ W2 + b2)
//   out[b,n,p] = max_{j,k} u   (p<8) ;  mean_{j,k} u  (p>=8)
//
// pre_kernel (129 blocks): W1 staged in SMEM; blocks 0..127 emit the w-image
//   g_wh[bn][kt][g][t4] (f16x2 fragment layout), block 128 emits the u1-image
//   and zeroes d_out.
// main_kernel: 4096 CTAs = (b,n) x 8 j-octets, 128 thr, 9 CTAs/SM.
//   Per 16x16 tile: 1 LDS.128 + 4 HADD2 + 4 HMAX2 + HMMA(f32 max-half)
//   + HMMA(f16 mean-half) + 4 FMNMX + 2 HMAX2 + 2 HADD2.
//   Partials merged atomicMax(bits)/atomicAdd.
// ============================================================================

__device__ uint4 g_wh[512 * 8 * 8 * 4];   // [bn][kt][g][t4] -> 2MB
__device__ uint2 g_u1h[2 * 128 * 4];      // [b][j][t4]

__device__ __forceinline__ uint32_t h2u(__half2 h) {
    return *reinterpret_cast<uint32_t*>(&h);
}
__device__ __forceinline__ uint32_t pack_h2(float lo, float hi) {
    __half2 h = __floats2half2_rn(lo, hi);
    return h2u(h);
}

// D(f32) = A*B + {c0,c1,c0,c1}
__device__ __forceinline__ void mma_f32_bias(float d[4],
                                             uint32_t a0, uint32_t a1, uint32_t a2, uint32_t a3,
                                             uint32_t b0, uint32_t b1, float c0, float c1) {
    asm("mma.sync.aligned.m16n8k16.row.col.f32.f16.f16.f32 "
        "{%0,%1,%2,%3}, {%4,%5,%6,%7}, {%8,%9}, {%10,%11,%10,%11};\n"
        : "=f"(d[0]), "=f"(d[1]), "=f"(d[2]), "=f"(d[3])
        : "r"(a0), "r"(a1), "r"(a2), "r"(a3), "r"(b0), "r"(b1), "f"(c0), "f"(c1));
}

// D(f16x2 x2) = A*B + {c,c}
__device__ __forceinline__ void mma_f16_bias(uint32_t d[2],
                                             uint32_t a0, uint32_t a1, uint32_t a2, uint32_t a3,
                                             uint32_t b0, uint32_t b1, uint32_t c) {
    asm("mma.sync.aligned.m16n8k16.row.col.f16.f16.f16.f16 "
        "{%0,%1}, {%2,%3,%4,%5}, {%6,%7}, {%8,%8};\n"
        : "=r"(d[0]), "=r"(d[1])
        : "r"(a0), "r"(a1), "r"(a2), "r"(a3), "r"(b0), "r"(b1), "r"(c));
}

// ============================================================================
// Fused pre kernel
// ============================================================================
__global__ void __launch_bounds__(256) pre_kernel(const float* __restrict__ x,
                                                  const float* __restrict__ x1,
                                                  const float* __restrict__ x2,
                                                  const float* __restrict__ W1,
                                                  const float* __restrict__ b1,
                                                  float* __restrict__ out) {
    __shared__ float sW1[768];
    const int t = threadIdx.x;
    #pragma unroll
    for (int i = 0; i < 3; ++i) sW1[t + i * 256] = W1[t + i * 256];
    __syncthreads();

    if (blockIdx.x < 128) {
        // ---- w-image for bn in [blk*4, blk*4+4) ----
        __shared__ float sU2[128][16];
        __shared__ float sBase[4][16];
        const int b = blockIdx.x >> 6;
        const int bn0 = blockIdx.x * 4;

        if (t < 128) {
            const float4* xr4 = (const float4*)(x2 + (b * 128 + t) * 16);
            float4 v0 = xr4[0], v1 = xr4[1], v2 = xr4[2], v3 = xr4[3];
            float xv[16] = {v0.x, v0.y, v0.z, v0.w, v1.x, v1.y, v1.z, v1.w,
                            v2.x, v2.y, v2.z, v2.w, v3.x, v3.y, v3.z, v3.w};
            #pragma unroll
            for (int o = 0; o < 16; ++o) {
                float s = 0.f;
                #pragma unroll
                for (int c = 0; c < 16; ++c)
                    s += xv[c] * sW1[(32 + c) * 16 + o];
                sU2[t][o] = s;
            }
        } else if (t < 192) {
            int bnl = (t - 128) >> 4, o = (t - 128) & 15;
            const float4* xr4 = (const float4*)(x + (bn0 + bnl) * 16);
            float4 v0 = xr4[0], v1 = xr4[1], v2 = xr4[2], v3 = xr4[3];
            float xv[16] = {v0.x, v0.y, v0.z, v0.w, v1.x, v1.y, v1.z, v1.w,
                            v2.x, v2.y, v2.z, v2.w, v3.x, v3.y, v3.z, v3.w};
            float s = b1[o];
            #pragma unroll
            for (int c = 0; c < 16; ++c)
                s += xv[c] * (sW1[c * 16 + o] - sW1[(16 + c) * 16 + o] - sW1[(32 + c) * 16 + o]);
            sBase[bnl][o] = s;
        }
        __syncthreads();

        // pack: thread = (bn_local, kt, g)
        const int bnl = t >> 6;
        const int rem = t & 63;
        const int kt = rem >> 3;
        const int g = rem & 7;
        const int r1 = kt * 16 + g;
        float w1[16], w2[16];
        #pragma unroll
        for (int o = 0; o < 16; ++o) {
            float bs = sBase[bnl][o];
            w1[o] = bs + sU2[r1][o];
            w2[o] = bs + sU2[r1 + 8][o];
        }
        uint4* dst = g_wh + (((bn0 + bnl) * 8 + kt) * 8 + g) * 4;
        #pragma unroll
        for (int t4 = 0; t4 < 4; ++t4) {
            uint4 e;
            e.x = pack_h2(w1[2 * t4],     w1[2 * t4 + 1]);   // row g,   cols lo
            e.y = pack_h2(w2[2 * t4],     w2[2 * t4 + 1]);   // row g+8, cols lo
            e.z = pack_h2(w1[2 * t4 + 8], w1[2 * t4 + 9]);   // row g,   cols hi
            e.w = pack_h2(w2[2 * t4 + 8], w2[2 * t4 + 9]);   // row g+8, cols hi
            dst[t4] = e;
        }
    } else {
        // ---- u1-image + zero d_out ----
        const int b = t >> 7;
        const int j = t & 127;
        const float4* xr4 = (const float4*)(x1 + (b * 128 + j) * 16);
        float4 v0 = xr4[0], v1 = xr4[1], v2 = xr4[2], v3 = xr4[3];
        float xv[16] = {v0.x, v0.y, v0.z, v0.w, v1.x, v1.y, v1.z, v1.w,
                        v2.x, v2.y, v2.z, v2.w, v3.x, v3.y, v3.z, v3.w};
        float u[16];
        #pragma unroll
        for (int o = 0; o < 16; ++o) {
            float s = 0.f;
            #pragma unroll
            for (int c = 0; c < 16; ++c)
                s += xv[c] * sW1[(16 + c) * 16 + o];
            u[o] = s;
        }
        uint2* dst = g_u1h + (b * 128 + j) * 4;
        #pragma unroll
        for (int t4 = 0; t4 < 4; ++t4) {
            uint2 e;
            e.x = pack_h2(u[2 * t4],     u[2 * t4 + 1]);
            e.y = pack_h2(u[2 * t4 + 8], u[2 * t4 + 9]);
            dst[t4] = e;
        }
        #pragma unroll
        for (int i = 0; i < 32; ++i)
            out[t + i * 256] = 0.f;
    }
}

// ============================================================================
// main kernel
// ============================================================================
__global__ void __launch_bounds__(128, 9)
main_kernel(const float* __restrict__ W2, const float* __restrict__ b2,
            float* __restrict__ out) {
    __shared__ uint4 sW[8][8][4];    // [kt][g][t4]  4KB
    __shared__ uint2 sU[16][4];      // [j_local][t4] 512B
    __shared__ float sRed[4][16];

    const int tid = threadIdx.x;
    const int wid = tid >> 5;
    const int lane = tid & 31;
    const int g = lane >> 2;
    const int t4 = lane & 3;
    const int bn = blockIdx.x >> 3;
    const int s = blockIdx.x & 7;    // j octet
    const int b = bn >> 8;

    // ---- SMEM setup: straight copies of pre-permuted images ----
    {
        const uint4* src = g_wh + bn * 256;
        uint4* dstW = &sW[0][0][0];
        dstW[tid] = src[tid];
        dstW[tid + 128] = src[tid + 128];
    }
    if (tid < 64) {
        ((uint2*)sU)[tid] = g_u1h[(b * 128 + s * 16) * 4 + tid];
    }

    // ---- B fragments (W2 -> f16 RN) + bias ----
    uint32_t Bf[2][2];
    #pragma unroll
    for (int nt = 0; nt < 2; ++nt) {
        int n = nt * 8 + g;
        Bf[nt][0] = pack_h2(W2[(2 * t4) * 16 + n],     W2[(2 * t4 + 1) * 16 + n]);
        Bf[nt][1] = pack_h2(W2[(2 * t4 + 8) * 16 + n], W2[(2 * t4 + 9) * 16 + n]);
    }
    const float bm0 = b2[2 * t4],     bm1 = b2[2 * t4 + 1];
    const uint32_t bsh = pack_h2(b2[8 + 2 * t4], b2[8 + 2 * t4 + 1]);

    float accm0 = 0.f, accm1 = 0.f;   // max half (f32, exact)
    float accs0 = 0.f, accs1 = 0.f;   // mean half (f32 master)
    const __half2 hz = __floats2half2_rn(0.f, 0.f);

    __syncthreads();

    // ---- main loop: 4 j x 8 k-tiles per warp ----
    #pragma unroll 1
    for (int jj = 0; jj < 4; ++jj) {
        const uint2 uu = sU[wid * 4 + jj][t4];
        const __half2 u_lo = *reinterpret_cast<const __half2*>(&uu.x);
        const __half2 u_hi = *reinterpret_cast<const __half2*>(&uu.y);
        __half2 macc0 = hz, macc1 = hz;   // f16 staged mean partials (8 tiles)
        #pragma unroll
        for (int kt = 0; kt < 8; ++kt) {
            const uint4 q = sW[kt][g][t4];
            // A = relu(w + u1) in f16x2 (fragment layout)
            uint32_t a0 = h2u(__hmax2(__hadd2(*reinterpret_cast<const __half2*>(&q.x), u_lo), hz));
            uint32_t a1 = h2u(__hmax2(__hadd2(*reinterpret_cast<const __half2*>(&q.y), u_lo), hz));
            uint32_t a2 = h2u(__hmax2(__hadd2(*reinterpret_cast<const __half2*>(&q.z), u_hi), hz));
            uint32_t a3 = h2u(__hmax2(__hadd2(*reinterpret_cast<const __half2*>(&q.w), u_hi), hz));

            float dm[4];
            uint32_t ds[2];
            mma_f32_bias(dm, a0, a1, a2, a3, Bf[0][0], Bf[0][1], bm0, bm1);
            mma_f16_bias(ds, a0, a1, a2, a3, Bf[1][0], Bf[1][1], bsh);

            // max half (relu folded: acc >= 0)
            accm0 = fmaxf(accm0, fmaxf(dm[0], dm[2]));
            accm1 = fmaxf(accm1, fmaxf(dm[1], dm[3]));
            // mean half: relu + packed f16 accumulate
            macc0 = __hadd2(macc0, __hmax2(*reinterpret_cast<const __half2*>(&ds[0]), hz));
            macc1 = __hadd2(macc1, __hmax2(*reinterpret_cast<const __half2*>(&ds[1]), hz));
        }
        // flush staged f16 partials to f32
        float2 f0 = __half22float2(macc0);
        float2 f1 = __half22float2(macc1);
        accs0 += f0.x + f1.x;
        accs1 += f0.y + f1.y;
    }

    // ---- intra-warp reduction over g lanes ----
    #pragma unroll
    for (int sh = 4; sh <= 16; sh <<= 1) {
        accm0 = fmaxf(accm0, __shfl_xor_sync(0xffffffffu, accm0, sh));
        accm1 = fmaxf(accm1, __shfl_xor_sync(0xffffffffu, accm1, sh));
        accs0 += __shfl_xor_sync(0xffffffffu, accs0, sh);
        accs1 += __shfl_xor_sync(0xffffffffu, accs1, sh);
    }
    if (lane < 4) {
        sRed[wid][2 * lane]         = accm0;
        sRed[wid][2 * lane + 1]     = accm1;
        sRed[wid][8 + 2 * lane]     = accs0;
        sRed[wid][8 + 2 * lane + 1] = accs1;
    }
    __syncthreads();

    // ---- cross-warp combine + atomic merge ----
    if (tid < 16) {
        float v = sRed[0][tid];
        if (tid < 8) {
            #pragma unroll
            for (int w = 1; w < 4; ++w) v = fmaxf(v, sRed[w][tid]);
            atomicMax((int*)(out + bn * 16 + tid), __float_as_int(v));  // v >= 0
        } else {
            #pragma unroll
            for (int w = 1; w < 4; ++w) v += sRed[w][tid];
            atomicAdd(out + bn * 16 + tid, v * (1.0f / 16384.0f));
        }
    }
}

// ============================================================================
// Launch
// ============================================================================
extern "C" void kernel_launch(void* const* d_in, const int* in_sizes, int n_in,
                              void* d_out, int out_size) {
    const float* x  = (const float*)d_in[0];
    const float* x1 = (const float*)d_in[1];
    const float* x2 = (const float*)d_in[2];
    const float* W1 = (const float*)d_in[3];
    const float* b1 = (const float*)d_in[4];
    const float* W2 = (const float*)d_in[5];
    const float* b2 = (const float*)d_in[6];
    float* out = (float*)d_out;

    pre_kernel<<<129, 256>>>(x, x1, x2, W1, b1, out);
    main_kernel<<<4096, 128>>>(W2, b2, out);
}

// round 11
// speedup vs baseline: 1.4545x; 1.4545x over previous
#include <cuda_runtime.h>
#include <cuda_fp16.h>
#include <cstdint>

// ============================================================================
// PointPairwiseRelation3 — fp16 mma.sync m16n8k16
//   A-gen via HADD2+HMAX2, mean-half via f16-out MMA + staged f16 accum
//   flushed to f32 every 8 tiles. 8 CTAs/SM (64-reg budget, no spills).
//
//   pre[b,n,j,k,o] = base[b,n,o] + U1[b,j,o] + U2[b,k,o]
//   h = relu(pre);  u = relu(h @ W2 + b2)
//   out[b,n,p] = max_{j,k} u   (p<8) ;  mean_{j,k} u  (p>=8)
//
// pre_kernel (129 blocks): W1 staged in SMEM; blocks 0..127 emit the w-image
//   g_wh[bn][kt][g][t4] (f16x2 fragment layout), block 128 emits the u1-image
//   and zeroes d_out.
// main_kernel: 4096 CTAs = (b,n) x 8 j-octets, 128 thr.
//   Per 16x16 tile: 1 LDS.128 + 4 HADD2 + 4 HMAX2 + HMMA(f32 max-half)
//   + HMMA(f16 mean-half) + 4 FMNMX + 2 HMAX2 + 2 HADD2.
//   Partials merged atomicMax(bits)/atomicAdd.
// ============================================================================

__device__ uint4 g_wh[512 * 8 * 8 * 4];   // [bn][kt][g][t4] -> 2MB
__device__ uint2 g_u1h[2 * 128 * 4];      // [b][j][t4]

__device__ __forceinline__ uint32_t h2u(__half2 h) {
    return *reinterpret_cast<uint32_t*>(&h);
}
__device__ __forceinline__ uint32_t pack_h2(float lo, float hi) {
    __half2 h = __floats2half2_rn(lo, hi);
    return h2u(h);
}

// D(f32) = A*B + {c0,c1,c0,c1}
__device__ __forceinline__ void mma_f32_bias(float d[4],
                                             uint32_t a0, uint32_t a1, uint32_t a2, uint32_t a3,
                                             uint32_t b0, uint32_t b1, float c0, float c1) {
    asm("mma.sync.aligned.m16n8k16.row.col.f32.f16.f16.f32 "
        "{%0,%1,%2,%3}, {%4,%5,%6,%7}, {%8,%9}, {%10,%11,%10,%11};\n"
        : "=f"(d[0]), "=f"(d[1]), "=f"(d[2]), "=f"(d[3])
        : "r"(a0), "r"(a1), "r"(a2), "r"(a3), "r"(b0), "r"(b1), "f"(c0), "f"(c1));
}

// D(f16x2 x2) = A*B + {c,c}
__device__ __forceinline__ void mma_f16_bias(uint32_t d[2],
                                             uint32_t a0, uint32_t a1, uint32_t a2, uint32_t a3,
                                             uint32_t b0, uint32_t b1, uint32_t c) {
    asm("mma.sync.aligned.m16n8k16.row.col.f16.f16.f16.f16 "
        "{%0,%1}, {%2,%3,%4,%5}, {%6,%7}, {%8,%8};\n"
        : "=r"(d[0]), "=r"(d[1])
        : "r"(a0), "r"(a1), "r"(a2), "r"(a3), "r"(b0), "r"(b1), "r"(c));
}

// ============================================================================
// Fused pre kernel
// ============================================================================
__global__ void __launch_bounds__(256) pre_kernel(const float* __restrict__ x,
                                                  const float* __restrict__ x1,
                                                  const float* __restrict__ x2,
                                                  const float* __restrict__ W1,
                                                  const float* __restrict__ b1,
                                                  float* __restrict__ out) {
    __shared__ float sW1[768];
    const int t = threadIdx.x;
    #pragma unroll
    for (int i = 0; i < 3; ++i) sW1[t + i * 256] = W1[t + i * 256];
    __syncthreads();

    if (blockIdx.x < 128) {
        // ---- w-image for bn in [blk*4, blk*4+4) ----
        __shared__ float sU2[128][16];
        __shared__ float sBase[4][16];
        const int b = blockIdx.x >> 6;
        const int bn0 = blockIdx.x * 4;

        if (t < 128) {
            const float4* xr4 = (const float4*)(x2 + (b * 128 + t) * 16);
            float4 v0 = xr4[0], v1 = xr4[1], v2 = xr4[2], v3 = xr4[3];
            float xv[16] = {v0.x, v0.y, v0.z, v0.w, v1.x, v1.y, v1.z, v1.w,
                            v2.x, v2.y, v2.z, v2.w, v3.x, v3.y, v3.z, v3.w};
            #pragma unroll
            for (int o = 0; o < 16; ++o) {
                float s = 0.f;
                #pragma unroll
                for (int c = 0; c < 16; ++c)
                    s += xv[c] * sW1[(32 + c) * 16 + o];
                sU2[t][o] = s;
            }
        } else if (t < 192) {
            int bnl = (t - 128) >> 4, o = (t - 128) & 15;
            const float4* xr4 = (const float4*)(x + (bn0 + bnl) * 16);
            float4 v0 = xr4[0], v1 = xr4[1], v2 = xr4[2], v3 = xr4[3];
            float xv[16] = {v0.x, v0.y, v0.z, v0.w, v1.x, v1.y, v1.z, v1.w,
                            v2.x, v2.y, v2.z, v2.w, v3.x, v3.y, v3.z, v3.w};
            float s = b1[o];
            #pragma unroll
            for (int c = 0; c < 16; ++c)
                s += xv[c] * (sW1[c * 16 + o] - sW1[(16 + c) * 16 + o] - sW1[(32 + c) * 16 + o]);
            sBase[bnl][o] = s;
        }
        __syncthreads();

        // pack: thread = (bn_local, kt, g)
        const int bnl = t >> 6;
        const int rem = t & 63;
        const int kt = rem >> 3;
        const int g = rem & 7;
        const int r1 = kt * 16 + g;
        float w1[16], w2[16];
        #pragma unroll
        for (int o = 0; o < 16; ++o) {
            float bs = sBase[bnl][o];
            w1[o] = bs + sU2[r1][o];
            w2[o] = bs + sU2[r1 + 8][o];
        }
        uint4* dst = g_wh + (((bn0 + bnl) * 8 + kt) * 8 + g) * 4;
        #pragma unroll
        for (int t4 = 0; t4 < 4; ++t4) {
            uint4 e;
            e.x = pack_h2(w1[2 * t4],     w1[2 * t4 + 1]);   // row g,   cols lo
            e.y = pack_h2(w2[2 * t4],     w2[2 * t4 + 1]);   // row g+8, cols lo
            e.z = pack_h2(w1[2 * t4 + 8], w1[2 * t4 + 9]);   // row g,   cols hi
            e.w = pack_h2(w2[2 * t4 + 8], w2[2 * t4 + 9]);   // row g+8, cols hi
            dst[t4] = e;
        }
    } else {
        // ---- u1-image + zero d_out ----
        const int b = t >> 7;
        const int j = t & 127;
        const float4* xr4 = (const float4*)(x1 + (b * 128 + j) * 16);
        float4 v0 = xr4[0], v1 = xr4[1], v2 = xr4[2], v3 = xr4[3];
        float xv[16] = {v0.x, v0.y, v0.z, v0.w, v1.x, v1.y, v1.z, v1.w,
                        v2.x, v2.y, v2.z, v2.w, v3.x, v3.y, v3.z, v3.w};
        float u[16];
        #pragma unroll
        for (int o = 0; o < 16; ++o) {
            float s = 0.f;
            #pragma unroll
            for (int c = 0; c < 16; ++c)
                s += xv[c] * sW1[(16 + c) * 16 + o];
            u[o] = s;
        }
        uint2* dst = g_u1h + (b * 128 + j) * 4;
        #pragma unroll
        for (int t4 = 0; t4 < 4; ++t4) {
            uint2 e;
            e.x = pack_h2(u[2 * t4],     u[2 * t4 + 1]);
            e.y = pack_h2(u[2 * t4 + 8], u[2 * t4 + 9]);
            dst[t4] = e;
        }
        #pragma unroll
        for (int i = 0; i < 32; ++i)
            out[t + i * 256] = 0.f;
    }
}

// ============================================================================
// main kernel
// ============================================================================
__global__ void __launch_bounds__(128, 8)
main_kernel(const float* __restrict__ W2, const float* __restrict__ b2,
            float* __restrict__ out) {
    __shared__ uint4 sW[8][8][4];    // [kt][g][t4]  4KB
    __shared__ uint2 sU[16][4];      // [j_local][t4] 512B
    __shared__ float sRed[4][16];

    const int tid = threadIdx.x;
    const int wid = tid >> 5;
    const int lane = tid & 31;
    const int g = lane >> 2;
    const int t4 = lane & 3;
    const int bn = blockIdx.x >> 3;
    const int s = blockIdx.x & 7;    // j octet
    const int b = bn >> 8;

    // ---- SMEM setup: straight copies of pre-permuted images ----
    {
        const uint4* src = g_wh + bn * 256;
        uint4* dstW = &sW[0][0][0];
        dstW[tid] = src[tid];
        dstW[tid + 128] = src[tid + 128];
    }
    if (tid < 64) {
        ((uint2*)sU)[tid] = g_u1h[(b * 128 + s * 16) * 4 + tid];
    }

    // ---- B fragments (W2 -> f16 RN) + bias ----
    uint32_t Bf[2][2];
    #pragma unroll
    for (int nt = 0; nt < 2; ++nt) {
        int n = nt * 8 + g;
        Bf[nt][0] = pack_h2(W2[(2 * t4) * 16 + n],     W2[(2 * t4 + 1) * 16 + n]);
        Bf[nt][1] = pack_h2(W2[(2 * t4 + 8) * 16 + n], W2[(2 * t4 + 9) * 16 + n]);
    }
    const float bm0 = b2[2 * t4],     bm1 = b2[2 * t4 + 1];
    const uint32_t bsh = pack_h2(b2[8 + 2 * t4], b2[8 + 2 * t4 + 1]);

    float accm0 = 0.f, accm1 = 0.f;   // max half (f32, exact)
    float accs0 = 0.f, accs1 = 0.f;   // mean half (f32 master)
    const __half2 hz = __floats2half2_rn(0.f, 0.f);

    __syncthreads();

    // ---- main loop: 4 j x 8 k-tiles per warp ----
    #pragma unroll 1
    for (int jj = 0; jj < 4; ++jj) {
        const uint2 uu = sU[wid * 4 + jj][t4];
        const __half2 u_lo = *reinterpret_cast<const __half2*>(&uu.x);
        const __half2 u_hi = *reinterpret_cast<const __half2*>(&uu.y);
        __half2 macc0 = hz, macc1 = hz;   // f16 staged mean partials (8 tiles)
        #pragma unroll
        for (int kt = 0; kt < 8; ++kt) {
            const uint4 q = sW[kt][g][t4];
            // A = relu(w + u1) in f16x2 (fragment layout)
            uint32_t a0 = h2u(__hmax2(__hadd2(*reinterpret_cast<const __half2*>(&q.x), u_lo), hz));
            uint32_t a1 = h2u(__hmax2(__hadd2(*reinterpret_cast<const __half2*>(&q.y), u_lo), hz));
            uint32_t a2 = h2u(__hmax2(__hadd2(*reinterpret_cast<const __half2*>(&q.z), u_hi), hz));
            uint32_t a3 = h2u(__hmax2(__hadd2(*reinterpret_cast<const __half2*>(&q.w), u_hi), hz));

            float dm[4];
            uint32_t ds[2];
            mma_f32_bias(dm, a0, a1, a2, a3, Bf[0][0], Bf[0][1], bm0, bm1);
            mma_f16_bias(ds, a0, a1, a2, a3, Bf[1][0], Bf[1][1], bsh);

            // max half (relu folded: acc >= 0)
            accm0 = fmaxf(accm0, fmaxf(dm[0], dm[2]));
            accm1 = fmaxf(accm1, fmaxf(dm[1], dm[3]));
            // mean half: relu + packed f16 accumulate
            macc0 = __hadd2(macc0, __hmax2(*reinterpret_cast<const __half2*>(&ds[0]), hz));
            macc1 = __hadd2(macc1, __hmax2(*reinterpret_cast<const __half2*>(&ds[1]), hz));
        }
        // flush staged f16 partials to f32
        float2 f0 = __half22float2(macc0);
        float2 f1 = __half22float2(macc1);
        accs0 += f0.x + f1.x;
        accs1 += f0.y + f1.y;
    }

    // ---- intra-warp reduction over g lanes ----
    #pragma unroll
    for (int sh = 4; sh <= 16; sh <<= 1) {
        accm0 = fmaxf(accm0, __shfl_xor_sync(0xffffffffu, accm0, sh));
        accm1 = fmaxf(accm1, __shfl_xor_sync(0xffffffffu, accm1, sh));
        accs0 += __shfl_xor_sync(0xffffffffu, accs0, sh);
        accs1 += __shfl_xor_sync(0xffffffffu, accs1, sh);
    }
    if (lane < 4) {
        sRed[wid][2 * lane]         = accm0;
        sRed[wid][2 * lane + 1]     = accm1;
        sRed[wid][8 + 2 * lane]     = accs0;
        sRed[wid][8 + 2 * lane + 1] = accs1;
    }
    __syncthreads();

    // ---- cross-warp combine + atomic merge ----
    if (tid < 16) {
        float v = sRed[0][tid];
        if (tid < 8) {
            #pragma unroll
            for (int w = 1; w < 4; ++w) v = fmaxf(v, sRed[w][tid]);
            atomicMax((int*)(out + bn * 16 + tid), __float_as_int(v));  // v >= 0
        } else {
            #pragma unroll
            for (int w = 1; w < 4; ++w) v += sRed[w][tid];
            atomicAdd(out + bn * 16 + tid, v * (1.0f / 16384.0f));
        }
    }
}

// ============================================================================
// Launch
// ============================================================================
extern "C" void kernel_launch(void* const* d_in, const int* in_sizes, int n_in,
                              void* d_out, int out_size) {
    const float* x  = (const float*)d_in[0];
    const float* x1 = (const float*)d_in[1];
    const float* x2 = (const float*)d_in[2];
    const float* W1 = (const float*)d_in[3];
    const float* b1 = (const float*)d_in[4];
    const float* W2 = (const float*)d_in[5];
    const float* b2 = (const float*)d_in[6];
    float* out = (float*)d_out;

    pre_kernel<<<129, 256>>>(x, x1, x2, W1, b1, out);
    main_kernel<<<4096, 128>>>(W2, b2, out);
}

// round 14
// speedup vs baseline: 1.5734x; 1.0817x over previous
#include <cuda_runtime.h>
#include <cuda_fp16.h>
#include <cstdint>

// ============================================================================
// PointPairwiseRelation3 — fp16 mma.sync m16n8k16, all-f16 MMA outputs
//
//   pre[b,n,j,k,o] = base[b,n,o] + U1[b,j,o] + U2[b,k,o]
//   h = relu(pre);  u = relu(h @ W2 + b2)
//   out[b,n,p] = max_{j,k} u   (p<8) ;  mean_{j,k} u  (p>=8)
//
// pre_kernel (129 blocks): W1 staged in SMEM; blocks 0..127 emit the w-image
//   g_wh[bn][kt][g][t4] (f16x2 fragment layout), block 128 emits the u1-image
//   and zeroes d_out.
// main_kernel: 4096 CTAs = (b,n) x 8 j-octets, 128 thr, 8 CTAs/SM.
//   kt-outer / j-inner: one LDS.128 of sW[kt] serves 4 tiles; per tile
//   8 half A-gen + 2 HMMA(f16) + 2 HMAX2 (max) + 4 half (mean);
//   f16 mean partials flushed to f32 every 2 kt (8 tiles).
//   Partials merged atomicMax(bits)/atomicAdd.
// ============================================================================

__device__ uint4 g_wh[512 * 8 * 8 * 4];   // [bn][kt][g][t4] -> 2MB
__device__ uint2 g_u1h[2 * 128 * 4];      // [b][j][t4]

__device__ __forceinline__ uint32_t h2u(__half2 h) {
    return *reinterpret_cast<uint32_t*>(&h);
}
__device__ __forceinline__ uint32_t pack_h2(float lo, float hi) {
    __half2 h = __floats2half2_rn(lo, hi);
    return h2u(h);
}
__device__ __forceinline__ __half2 u2h(uint32_t u) {
    return *reinterpret_cast<__half2*>(&u);
}

// D(f16x2 x2) = A*B + {c,c}
__device__ __forceinline__ void mma_f16_bias(uint32_t d[2],
                                             uint32_t a0, uint32_t a1, uint32_t a2, uint32_t a3,
                                             uint32_t b0, uint32_t b1, uint32_t c) {
    asm("mma.sync.aligned.m16n8k16.row.col.f16.f16.f16.f16 "
        "{%0,%1}, {%2,%3,%4,%5}, {%6,%7}, {%8,%8};\n"
        : "=r"(d[0]), "=r"(d[1])
        : "r"(a0), "r"(a1), "r"(a2), "r"(a3), "r"(b0), "r"(b1), "r"(c));
}

// ============================================================================
// Fused pre kernel
// ============================================================================
__global__ void __launch_bounds__(256) pre_kernel(const float* __restrict__ x,
                                                  const float* __restrict__ x1,
                                                  const float* __restrict__ x2,
                                                  const float* __restrict__ W1,
                                                  const float* __restrict__ b1,
                                                  float* __restrict__ out) {
    __shared__ float sW1[768];
    const int t = threadIdx.x;
    #pragma unroll
    for (int i = 0; i < 3; ++i) sW1[t + i * 256] = W1[t + i * 256];
    __syncthreads();

    if (blockIdx.x < 128) {
        // ---- w-image for bn in [blk*4, blk*4+4) ----
        __shared__ float sU2[128][16];
        __shared__ float sBase[4][16];
        const int b = blockIdx.x >> 6;
        const int bn0 = blockIdx.x * 4;

        if (t < 128) {
            const float4* xr4 = (const float4*)(x2 + (b * 128 + t) * 16);
            float4 v0 = xr4[0], v1 = xr4[1], v2 = xr4[2], v3 = xr4[3];
            float xv[16] = {v0.x, v0.y, v0.z, v0.w, v1.x, v1.y, v1.z, v1.w,
                            v2.x, v2.y, v2.z, v2.w, v3.x, v3.y, v3.z, v3.w};
            #pragma unroll
            for (int o = 0; o < 16; ++o) {
                float s = 0.f;
                #pragma unroll
                for (int c = 0; c < 16; ++c)
                    s += xv[c] * sW1[(32 + c) * 16 + o];
                sU2[t][o] = s;
            }
        } else if (t < 192) {
            int bnl = (t - 128) >> 4, o = (t - 128) & 15;
            const float4* xr4 = (const float4*)(x + (bn0 + bnl) * 16);
            float4 v0 = xr4[0], v1 = xr4[1], v2 = xr4[2], v3 = xr4[3];
            float xv[16] = {v0.x, v0.y, v0.z, v0.w, v1.x, v1.y, v1.z, v1.w,
                            v2.x, v2.y, v2.z, v2.w, v3.x, v3.y, v3.z, v3.w};
            float s = b1[o];
            #pragma unroll
            for (int c = 0; c < 16; ++c)
                s += xv[c] * (sW1[c * 16 + o] - sW1[(16 + c) * 16 + o] - sW1[(32 + c) * 16 + o]);
            sBase[bnl][o] = s;
        }
        __syncthreads();

        // pack: thread = (bn_local, kt, g)
        const int bnl = t >> 6;
        const int rem = t & 63;
        const int kt = rem >> 3;
        const int g = rem & 7;
        const int r1 = kt * 16 + g;
        float w1[16], w2[16];
        #pragma unroll
        for (int o = 0; o < 16; ++o) {
            float bs = sBase[bnl][o];
            w1[o] = bs + sU2[r1][o];
            w2[o] = bs + sU2[r1 + 8][o];
        }
        uint4* dst = g_wh + (((bn0 + bnl) * 8 + kt) * 8 + g) * 4;
        #pragma unroll
        for (int t4 = 0; t4 < 4; ++t4) {
            uint4 e;
            e.x = pack_h2(w1[2 * t4],     w1[2 * t4 + 1]);   // row g,   cols lo
            e.y = pack_h2(w2[2 * t4],     w2[2 * t4 + 1]);   // row g+8, cols lo
            e.z = pack_h2(w1[2 * t4 + 8], w1[2 * t4 + 9]);   // row g,   cols hi
            e.w = pack_h2(w2[2 * t4 + 8], w2[2 * t4 + 9]);   // row g+8, cols hi
            dst[t4] = e;
        }
    } else {
        // ---- u1-image + zero d_out ----
        const int b = t >> 7;
        const int j = t & 127;
        const float4* xr4 = (const float4*)(x1 + (b * 128 + j) * 16);
        float4 v0 = xr4[0], v1 = xr4[1], v2 = xr4[2], v3 = xr4[3];
        float xv[16] = {v0.x, v0.y, v0.z, v0.w, v1.x, v1.y, v1.z, v1.w,
                        v2.x, v2.y, v2.z, v2.w, v3.x, v3.y, v3.z, v3.w};
        float u[16];
        #pragma unroll
        for (int o = 0; o < 16; ++o) {
            float s = 0.f;
            #pragma unroll
            for (int c = 0; c < 16; ++c)
                s += xv[c] * sW1[(16 + c) * 16 + o];
            u[o] = s;
        }
        uint2* dst = g_u1h + (b * 128 + j) * 4;
        #pragma unroll
        for (int t4 = 0; t4 < 4; ++t4) {
            uint2 e;
            e.x = pack_h2(u[2 * t4],     u[2 * t4 + 1]);
            e.y = pack_h2(u[2 * t4 + 8], u[2 * t4 + 9]);
            dst[t4] = e;
        }
        #pragma unroll
        for (int i = 0; i < 32; ++i)
            out[t + i * 256] = 0.f;
    }
}

// ============================================================================
// main kernel
// ============================================================================
__global__ void __launch_bounds__(128, 8)
main_kernel(const float* __restrict__ W2, const float* __restrict__ b2,
            float* __restrict__ out) {
    __shared__ uint4 sW[8][8][4];    // [kt][g][t4]  4KB
    __shared__ uint2 sU[16][4];      // [j_local][t4] 512B
    __shared__ float sRed[4][16];

    const int tid = threadIdx.x;
    const int wid = tid >> 5;
    const int lane = tid & 31;
    const int g = lane >> 2;
    const int t4 = lane & 3;
    const int bn = blockIdx.x >> 3;
    const int s = blockIdx.x & 7;    // j octet
    const int b = bn >> 8;

    // ---- SMEM setup: straight copies of pre-permuted images ----
    {
        const uint4* src = g_wh + bn * 256;
        uint4* dstW = &sW[0][0][0];
        dstW[tid] = src[tid];
        dstW[tid + 128] = src[tid + 128];
    }
    if (tid < 64) {
        ((uint2*)sU)[tid] = g_u1h[(b * 128 + s * 16) * 4 + tid];
    }

    // ---- B fragments (W2 -> f16 RN) + f16 biases ----
    uint32_t Bf[2][2];
    #pragma unroll
    for (int nt = 0; nt < 2; ++nt) {
        int n = nt * 8 + g;
        Bf[nt][0] = pack_h2(W2[(2 * t4) * 16 + n],     W2[(2 * t4 + 1) * 16 + n]);
        Bf[nt][1] = pack_h2(W2[(2 * t4 + 8) * 16 + n], W2[(2 * t4 + 9) * 16 + n]);
    }
    const uint32_t bmh = pack_h2(b2[2 * t4],     b2[2 * t4 + 1]);
    const uint32_t bsh = pack_h2(b2[8 + 2 * t4], b2[8 + 2 * t4 + 1]);

    const __half2 hz = __floats2half2_rn(0.f, 0.f);
    __half2 maccm = hz;               // max accum, f16 for whole loop (exact-ish)
    float accs0 = 0.f, accs1 = 0.f;   // mean master accum (f32)

    __syncthreads();

    // ---- this warp's 4 U1 fragments (held in regs) ----
    uint32_t u_lo[4], u_hi[4];
    #pragma unroll
    for (int j = 0; j < 4; ++j) {
        uint2 uu = sU[wid * 4 + j][t4];
        u_lo[j] = uu.x;
        u_hi[j] = uu.y;
    }

    // ---- main loop: kt outer (1 LDS serves 4 j-tiles), j inner ----
    __half2 maccs = hz;               // staged f16 mean partials (2 kt = 8 tiles)
    #pragma unroll
    for (int kt = 0; kt < 8; ++kt) {
        const uint4 q = sW[kt][g][t4];
        #pragma unroll
        for (int j = 0; j < 4; ++j) {
            // A = relu(w + u1) in f16x2 (fragment layout)
            uint32_t a0 = h2u(__hmax2(__hadd2(u2h(q.x), u2h(u_lo[j])), hz));
            uint32_t a1 = h2u(__hmax2(__hadd2(u2h(q.y), u2h(u_lo[j])), hz));
            uint32_t a2 = h2u(__hmax2(__hadd2(u2h(q.z), u2h(u_hi[j])), hz));
            uint32_t a3 = h2u(__hmax2(__hadd2(u2h(q.w), u2h(u_hi[j])), hz));

            uint32_t dm[2], ds[2];
            mma_f16_bias(dm, a0, a1, a2, a3, Bf[0][0], Bf[0][1], bmh);
            mma_f16_bias(ds, a0, a1, a2, a3, Bf[1][0], Bf[1][1], bsh);

            // max half (relu folded: acc >= 0)
            maccm = __hmax2(maccm, __hmax2(u2h(dm[0]), u2h(dm[1])));
            // mean half: relu + packed f16 accumulate
            maccs = __hadd2(maccs, __hmax2(u2h(ds[0]), hz));
            maccs = __hadd2(maccs, __hmax2(u2h(ds[1]), hz));
        }
        if (kt & 1) {   // flush staged f16 mean partials every 2 kt (8 tiles)
            float2 f = __half22float2(maccs);
            accs0 += f.x;
            accs1 += f.y;
            maccs = hz;
        }
    }

    float2 fm = __half22float2(maccm);
    float accm0 = fm.x, accm1 = fm.y;

    // ---- intra-warp reduction over g lanes ----
    #pragma unroll
    for (int sh = 4; sh <= 16; sh <<= 1) {
        accm0 = fmaxf(accm0, __shfl_xor_sync(0xffffffffu, accm0, sh));
        accm1 = fmaxf(accm1, __shfl_xor_sync(0xffffffffu, accm1, sh));
        accs0 += __shfl_xor_sync(0xffffffffu, accs0, sh);
        accs1 += __shfl_xor_sync(0xffffffffu, accs1, sh);
    }
    if (lane < 4) {
        sRed[wid][2 * lane]         = accm0;
        sRed[wid][2 * lane + 1]     = accm1;
        sRed[wid][8 + 2 * lane]     = accs0;
        sRed[wid][8 + 2 * lane + 1] = accs1;
    }
    __syncthreads();

    // ---- cross-warp combine + atomic merge ----
    if (tid < 16) {
        float v = sRed[0][tid];
        if (tid < 8) {
            #pragma unroll
            for (int w = 1; w < 4; ++w) v = fmaxf(v, sRed[w][tid]);
            atomicMax((int*)(out + bn * 16 + tid), __float_as_int(v));  // v >= 0
        } else {
            #pragma unroll
            for (int w = 1; w < 4; ++w) v += sRed[w][tid];
            atomicAdd(out + bn * 16 + tid, v * (1.0f / 16384.0f));
        }
    }
}

// ============================================================================
// Launch
// ============================================================================
extern "C" void kernel_launch(void* const* d_in, const int* in_sizes, int n_in,
                              void* d_out, int out_size) {
    const float* x  = (const float*)d_in[0];
    const float* x1 = (const float*)d_in[1];
    const float* x2 = (const float*)d_in[2];
    const float* W1 = (const float*)d_in[3];
    const float* b1 = (const float*)d_in[4];
    const float* W2 = (const float*)d_in[5];
    const float* b2 = (const float*)d_in[6];
    float* out = (float*)d_out;

    pre_kernel<<<129, 256>>>(x, x1, x2, W1, b1, out);
    main_kernel<<<4096, 128>>>(W2, b2, out);
}